// round 6
// baseline (speedup 1.0000x reference)
#include <cuda_runtime.h>
#include <stdint.h>

// LengthRegulator split into:
//   1) lr_index_kernel: per-(n) duration scan + per-t binary search ->
//      g_idx[n][t] (device global), plus mel_pos tail. Tiny.
//   2) lr_copy_kernel: pure gather-copy. No smem, no barriers. Thread owns a
//      channel chunk and walks 8 consecutive frames, register-caching the
//      source float4 (consecutive frames share a source row ~88%).
//
// Output layout (validated via out_size divisibility, N*C = 24576):
//   case A: [ out: N*T*C f32 ][ mel_pos: T f32 ]
//   case B: [ out: N*T*C f32 ][ mel_pos: T i64 ]

#define L_LEN   256
#define FRAMES  24            // 3 groups x 8 frames per block
#define FPG     8
#define NMAX    64
#define TMAX    4224          // max possible T (16*256=4096) + padding

__device__ int g_idx[NMAX * TMAX];

__global__ __launch_bounds__(256)
void lr_index_kernel(const int* __restrict__ dur,
                     float* __restrict__ mp,
                     int T, int mel_is_i64)
{
    const int n    = blockIdx.x;
    const int tb   = blockIdx.y * 1024;
    const int tid  = threadIdx.x;
    const int wid  = tid >> 5;
    const int lane = tid & 31;

    __shared__ int csum[L_LEN];
    __shared__ int wsum[8];

    // inclusive prefix sum of durations for row n (shuffle scan)
    int v = dur[n * L_LEN + tid];
    #pragma unroll
    for (int off = 1; off < 32; off <<= 1) {
        int u = __shfl_up_sync(0xFFFFFFFFu, v, off);
        if (lane >= off) v += u;
    }
    if (lane == 31) wsum[wid] = v;
    __syncthreads();
    if (wid == 0 && lane < 8) {
        int s = wsum[lane];
        #pragma unroll
        for (int off = 1; off < 8; off <<= 1) {
            int u = __shfl_up_sync(0xFFu, s, off);
            if (lane >= off) s += u;
        }
        wsum[lane] = s;
    }
    __syncthreads();
    csum[tid] = v + (wid > 0 ? wsum[wid - 1] : 0);
    __syncthreads();

    const int total = csum[L_LEN - 1];

    // 4 searches per thread, coalesced t ranges
    #pragma unroll
    for (int i = 0; i < 4; i++) {
        int t = tb + i * 256 + tid;
        if (t < T) {
            int id = -1;
            if (t < total) {
                int lo = 0, hi = L_LEN;
                while (lo < hi) {
                    int mid = (lo + hi) >> 1;
                    if (csum[mid] > t) hi = mid; else lo = mid + 1;
                }
                id = (lo < L_LEN) ? lo : (L_LEN - 1);
            }
            g_idx[n * TMAX + t] = id;
            if (n == 0) {
                if (mel_is_i64) ((long long*)mp)[t] = (long long)(t + 1);
                else            mp[t] = (float)(t + 1);
            }
        }
    }
}

__global__ __launch_bounds__(512)
void lr_copy_kernel(const float* __restrict__ x,
                    float* __restrict__ out,
                    int T, int vec)   // vec = C/4 (96)
{
    const int n   = blockIdx.y;
    const int t0  = blockIdx.x * FRAMES;
    const int tid = threadIdx.x;
    const int g   = tid / 96;          // 0..2  (vec == 96 for C == 384)
    const int c   = tid - g * 96;

    const float4* xv = (const float4*)(x + (size_t)n * L_LEN * (vec * 4));
    float4*       ov = (float4*)(out + ((size_t)n * T + t0) * (vec * 4));
    const float4  z  = make_float4(0.f, 0.f, 0.f, 0.f);

    const int fb = g * FPG;
    // preload this group's 8 frame ids (t0, fb both multiples of 8 -> aligned)
    const int4* ip = (const int4*)&g_idx[n * TMAX + t0 + fb];
    const int4 ia = ip[0];
    const int4 ib = ip[1];
    const int ids[FPG] = { ia.x, ia.y, ia.z, ia.w, ib.x, ib.y, ib.z, ib.w };

    int    cur = -2;
    float4 val = z;

    #pragma unroll
    for (int i = 0; i < FPG; i++) {
        const int f = fb + i;
        const int t = t0 + f;
        if (t >= T) break;
        const int id = ids[i];
        if (id != cur) {               // warp-uniform (whole warp in one group)
            val = (id >= 0) ? __ldg(&xv[(size_t)id * 96 + c]) : z;
            cur = id;
        }
        ov[(size_t)f * 96 + c] = val;
    }
}

extern "C" void kernel_launch(void* const* d_in, const int* in_sizes, int n_in,
                              void* d_out, int out_size)
{
    const float* x   = (const float*)d_in[0];
    const int*   dur = (const int*)d_in[1];

    const int NL = in_sizes[1];            // N * L
    const int N  = NL / L_LEN;             // 64
    const int C  = in_sizes[0] / NL;       // 384
    const int vec = C / 4;                 // 96

    const long long S    = (long long)out_size;
    const long long base = (long long)N * C;

    int T;
    int mel_is_i64 = 0;
    if (S % (base + 1) == 0) {
        T = (int)(S / (base + 1));         // case A: mel_pos as f32
    } else if (S % (base + 2) == 0) {
        T = (int)(S / (base + 2));         // case B: mel_pos as i64
        mel_is_i64 = 1;
    } else {
        T = (int)(S / base);               // fallback
    }

    float* out  = (float*)d_out;
    float* tail = out + (size_t)N * T * C;

    // 1) index precompute + mel_pos
    dim3 ig(N, (T + 1023) / 1024);
    lr_index_kernel<<<ig, 256>>>(dur, tail, T, mel_is_i64);

    // 2) pure streaming gather-copy
    dim3 cg((T + FRAMES - 1) / FRAMES, N);
    lr_copy_kernel<<<cg, 3 * vec>>>(x, out, T, vec);
}

// round 7
// speedup vs baseline: 1.0816x; 1.0816x over previous
#include <cuda_runtime.h>
#include <stdint.h>

// LengthRegulator, single-kernel one-wave design.
//   out[n, t, :] = x[n, searchsorted(csum[n], t, 'right'), :] for t < total[n], else 0
//   mel_pos = [1..T] appended after the frames.
//
// Output layout (validated via out_size divisibility, N*C = 24576):
//   case A: [ out: N*T*C f32 ][ mel_pos: T f32 ]
//   case B: [ out: N*T*C f32 ][ mel_pos: T i64 ]
//
// Grid = (N, SLICES) = (64, 16) = 1024 blocks x 288 threads -> ~2016 thr/SM:
// the ENTIRE grid is resident in one wave, so the scan+search prologue is paid
// once concurrently, not once per wave. Each block owns ~T/16 consecutive
// frames; a thread owns one float4 channel chunk and walks ~fpb/3 consecutive
// frames, register-caching its source float4 (mean duration 8.5 -> ~1 reload
// per 8.5 frames). Output stores use evict-first (.cs) streaming hints.

#define L_LEN    256
#define THREADS  288           // 3 groups x 96 channel chunks
#define SLICES   16
#define FMAX     272           // max frames per block (T <= 4096 -> fpb <= 256)

__global__ __launch_bounds__(THREADS)
void lr_onewave_kernel(const float* __restrict__ x,
                       const int* __restrict__ dur,
                       float* __restrict__ out,
                       float* __restrict__ mp,
                       int T, int mel_is_i64)
{
    const int n    = blockIdx.x;
    const int s    = blockIdx.y;
    const int tid  = threadIdx.x;
    const int wid  = tid >> 5;
    const int lane = tid & 31;

    const int fpb     = (T + SLICES - 1) / SLICES;     // frames per block
    const int t_begin = s * fpb;
    const int t_end   = (t_begin + fpb < T) ? (t_begin + fpb) : T;
    const int nf      = t_end - t_begin;               // may be <= 0 for tail
    if (nf <= 0) return;

    __shared__ int csum[L_LEN];
    __shared__ int wsum[8];
    __shared__ int fidx[FMAX];

    // ---- mel_pos: row-0 blocks write their slice ----
    if (n == 0) {
        for (int f = tid; f < nf; f += THREADS) {
            int t = t_begin + f;
            if (mel_is_i64) ((long long*)mp)[t] = (long long)(t + 1);
            else            mp[t] = (float)(t + 1);
        }
    }

    // ---- inclusive prefix sum of durations (shuffle scan, warps 0..7) ----
    int v = 0;
    if (tid < L_LEN) {
        v = dur[n * L_LEN + tid];
        #pragma unroll
        for (int off = 1; off < 32; off <<= 1) {
            int u = __shfl_up_sync(0xFFFFFFFFu, v, off);
            if (lane >= off) v += u;
        }
        if (lane == 31) wsum[wid] = v;
    }
    __syncthreads();
    if (wid == 0 && lane < 8) {
        int t = wsum[lane];
        #pragma unroll
        for (int off = 1; off < 8; off <<= 1) {
            int u = __shfl_up_sync(0xFFu, t, off);
            if (lane >= off) t += u;
        }
        wsum[lane] = t;
    }
    __syncthreads();
    if (tid < L_LEN) csum[tid] = v + (wid > 0 ? wsum[wid - 1] : 0);
    __syncthreads();

    const int total = csum[L_LEN - 1];

    // ---- binary search source row for each frame of this chunk ----
    for (int f = tid; f < nf; f += THREADS) {
        int t  = t_begin + f;
        int id = -1;
        if (t < total) {
            int lo = 0, hi = L_LEN;
            while (lo < hi) {
                int mid = (lo + hi) >> 1;
                if (csum[mid] > t) hi = mid; else lo = mid + 1;
            }
            id = (lo < L_LEN) ? lo : (L_LEN - 1);
        }
        fidx[f] = id;
    }
    __syncthreads();

    // ---- streaming copy with register-cached source float4 ----
    const int g = tid / 96;                // frame-group 0..2 (whole warps)
    const int c = tid - g * 96;            // channel chunk 0..95

    const int fpg = (nf + 2) / 3;
    const int f0  = g * fpg;
    const int f1  = (f0 + fpg < nf) ? (f0 + fpg) : nf;

    const float4* xv = (const float4*)(x + (size_t)n * L_LEN * 384);
    float4*       ov = (float4*)(out + ((size_t)n * T + t_begin) * 384) + c;
    const float4  z  = make_float4(0.f, 0.f, 0.f, 0.f);

    int    cur = -2;
    float4 val = z;

    float4* dst = ov + (size_t)f0 * 96;
    for (int f = f0; f < f1; f++, dst += 96) {
        const int id = fidx[f];
        if (id != cur) {                   // warp-uniform (warp in one group)
            val = (id >= 0) ? __ldg(&xv[(size_t)id * 96 + c]) : z;
            cur = id;
        }
        __stcs(dst, val);                  // evict-first streaming store
    }
}

extern "C" void kernel_launch(void* const* d_in, const int* in_sizes, int n_in,
                              void* d_out, int out_size)
{
    const float* x   = (const float*)d_in[0];
    const int*   dur = (const int*)d_in[1];

    const int NL = in_sizes[1];            // N * L
    const int N  = NL / L_LEN;             // 64
    const int C  = in_sizes[0] / NL;       // 384 (layout assumes 384)

    const long long S    = (long long)out_size;
    const long long base = (long long)N * C;

    int T;
    int mel_is_i64 = 0;
    if (S % (base + 1) == 0) {
        T = (int)(S / (base + 1));         // case A: mel_pos as f32
    } else if (S % (base + 2) == 0) {
        T = (int)(S / (base + 2));         // case B: mel_pos as i64
        mel_is_i64 = 1;
    } else {
        T = (int)(S / base);               // fallback
    }

    float* out  = (float*)d_out;
    float* tail = out + (size_t)N * T * C;

    dim3 grid(N, SLICES);
    lr_onewave_kernel<<<grid, THREADS>>>(x, dur, out, tail, T, mel_is_i64);
}